// round 15
// baseline (speedup 1.0000x reference)
#include <cuda_runtime.h>
#include <cuda_fp16.h>
#include <cstdint>

#define NROWS 4096      // B*T
#define VOCAB 32000
#define UNITS 64
#define GATES 256
#define EMBED 512
#define TT 128
#define NB 32

#define BM 128
#define BN 128
#define NT (VOCAB / BN)          // 250 col tiles
#define TPC 10                   // col tiles per CTA
#define NCT (NT / TPC)           // 25 CTAs along x
#define PADK 136

#define AS_BYTES (BM * PADK * 2)     // 34816
#define BS_BYTES (BN * PADK * 2)     // 34816
#define SMEM_MMA (AS_BYTES + 2 * BS_BYTES)   // 104448

// ---------------- device scratch ----------------
__device__ __align__(256) float g_xz[NROWS * GATES];
__device__ __align__(256) float g_hs[NROWS * UNITS];
__device__ __align__(256) __half g_Ah[NROWS * 128];            // feat fp16
__device__ __align__(256) __half g_Wh[(size_t)VOCAB * 128];    // Wd^T fp16
__device__ __align__(256) __half g_eh[(size_t)NROWS * VOCAB];  // exp fp16
__device__ __align__(256) float g_partial[(size_t)NT * 4 * NROWS];  // 16.7 MB
__device__ __align__(256) float g_inv[NROWS];

__device__ __forceinline__ void mma_f16(float* c, const uint32_t* a,
                                        const uint32_t* b) {
    asm volatile(
        "mma.sync.aligned.m16n8k16.row.col.f32.f16.f16.f32 "
        "{%0,%1,%2,%3}, {%4,%5,%6,%7}, {%8,%9}, {%0,%1,%2,%3};"
        : "+f"(c[0]), "+f"(c[1]), "+f"(c[2]), "+f"(c[3])
        : "r"(a[0]), "r"(a[1]), "r"(a[2]), "r"(a[3]), "r"(b[0]), "r"(b[1]));
}
__device__ __forceinline__ void ldm_x4(uint32_t* r, uint32_t addr) {
    asm volatile("ldmatrix.sync.aligned.m8n8.x4.shared.b16 {%0,%1,%2,%3}, [%4];"
                 : "=r"(r[0]), "=r"(r[1]), "=r"(r[2]), "=r"(r[3]) : "r"(addr));
}
__device__ __forceinline__ uint32_t smem_u32(const void* p) {
    uint32_t a;
    asm("{ .reg .u64 t; cvta.to.shared.u64 t, %1; cvt.u32.u64 %0, t; }"
        : "=r"(a) : "l"(p));
    return a;
}
__device__ __forceinline__ void cp16(uint32_t dst, const void* src) {
    asm volatile("cp.async.ca.shared.global [%0], [%1], 16;"
                 :: "r"(dst), "l"(src) : "memory");
}
#define CP_COMMIT() asm volatile("cp.async.commit_group;" ::: "memory")
#define CP_WAIT0()  asm volatile("cp.async.wait_group 0;" ::: "memory")
#define CP_WAIT1()  asm volatile("cp.async.wait_group 1;" ::: "memory")

// ---------------- kernel: Wd [128][32000] f32 -> g_Wh [32000][128] fp16 ----
__global__ __launch_bounds__(256) void k_cvtWd(const float* __restrict__ Wd) {
    __shared__ float sm[32][33];
    int tx = threadIdx.x & 31, ty = threadIdx.x >> 5;
    int v0 = blockIdx.x * 32, k0 = blockIdx.y * 32;
#pragma unroll
    for (int i = 0; i < 4; i++) {
        int k = ty + i * 8;
        sm[k][tx] = Wd[(size_t)(k0 + k) * VOCAB + v0 + tx];
    }
    __syncthreads();
#pragma unroll
    for (int i = 0; i < 4; i++) {
        int vl = ty + i * 8;
        g_Wh[(size_t)(v0 + vl) * 128 + k0 + tx] = __float2half(sm[tx][vl]);
    }
}

// ---------------- kernel A: xz = emb[dec] @ Wx + b ----------------
__global__ __launch_bounds__(256) void k_xz(const int* __restrict__ dec,
                                            const float* __restrict__ emb,
                                            const float* __restrict__ Wx,
                                            const float* __restrict__ bvec) {
    __shared__ float xs[16 * EMBED];
    __shared__ int tok[16];
    int tid = threadIdx.x;
    int rowBase = blockIdx.x * 16;
    if (tid < 16) tok[tid] = dec[rowBase + tid];
    __syncthreads();
    for (int i = tid; i < 16 * (EMBED / 4); i += 256) {
        int r = i >> 7, q = i & 127;
        ((float4*)xs)[r * (EMBED / 4) + q] =
            ((const float4*)(emb + (size_t)tok[r] * EMBED))[q];
    }
    __syncthreads();
    int g = tid;
    float bb = bvec[g];
    float acc[16];
#pragma unroll
    for (int r = 0; r < 16; r++) acc[r] = bb;
#pragma unroll 4
    for (int e = 0; e < EMBED; e++) {
        float w = Wx[e * GATES + g];
#pragma unroll
        for (int r = 0; r < 16; r++) acc[r] += xs[r * EMBED + e] * w;
    }
#pragma unroll
    for (int r = 0; r < 16; r++) g_xz[(size_t)(rowBase + r) * GATES + g] = acc[r];
}

// ---------------- kernel B: sequential LSTM ----------------
__global__ __launch_bounds__(256) void k_lstm(const float* __restrict__ h0,
                                              const float* __restrict__ c0,
                                              const float* __restrict__ Wh,
                                              float* __restrict__ tail) {
    int b = blockIdx.x;
    int g = threadIdx.x;
    float wh[UNITS];
#pragma unroll
    for (int u = 0; u < UNITS; u++) wh[u] = Wh[u * GATES + g];
    __shared__ __align__(16) float sh_h[UNITS];
    __shared__ float sh_z[GATES];
    float c = 0.f;
    if (g < UNITS) {
        sh_h[g] = h0[b * UNITS + g];
        c = c0[b * UNITS + g];
    }
    __syncthreads();
    for (int t = 0; t < TT; t++) {
        float z = g_xz[((size_t)b * TT + t) * GATES + g];
#pragma unroll
        for (int u4 = 0; u4 < UNITS / 4; u4++) {
            float4 h4 = ((const float4*)sh_h)[u4];
            z += h4.x * wh[u4 * 4] + h4.y * wh[u4 * 4 + 1] +
                 h4.z * wh[u4 * 4 + 2] + h4.w * wh[u4 * 4 + 3];
        }
        sh_z[g] = z;
        __syncthreads();
        if (g < UNITS) {
            float ig = 1.f / (1.f + expf(-sh_z[g]));
            float fg = 1.f / (1.f + expf(-sh_z[UNITS + g]));
            float gg = tanhf(sh_z[2 * UNITS + g]);
            float og = 1.f / (1.f + expf(-sh_z[3 * UNITS + g]));
            c = fg * c + ig * gg;
            float h = og * tanhf(c);
            sh_h[g] = h;
            g_hs[((size_t)b * TT + t) * UNITS + g] = h;
        }
        __syncthreads();
    }
    if (g < UNITS) {
        tail[b * UNITS + g] = sh_h[g];
        tail[NB * UNITS + b * UNITS + g] = c;
    }
}

// ---------------- kernel C: attention (per-b 16-t chunks) -> fp16 feat ----
__global__ __launch_bounds__(256) void k_attn(const float* __restrict__ enc,
                                              const float* __restrict__ h0) {
    __shared__ float encp[TT * 65];
    __shared__ float qs[16 * 64];
    __shared__ float att[16 * 128];
    int tid = threadIdx.x;
    int b = blockIdx.y, tc = blockIdx.x;
    const float* eb = enc + (size_t)b * TT * UNITS;
    for (int i = tid; i < TT * UNITS; i += 256) {
        int s = i >> 6, u = i & 63;
        encp[s * 65 + u] = eb[i];
    }
    for (int i = tid; i < 16 * 64; i += 256) {
        int tl = i >> 6, u = i & 63;
        int t = tc * 16 + tl;
        qs[i] = (t == 0) ? h0[b * 64 + u]
                         : g_hs[((size_t)b * TT + t - 1) * 64 + u];
    }
    __syncthreads();
    int w = tid >> 5, lane = tid & 31;
#pragma unroll 1
    for (int tt = 0; tt < 2; tt++) {
        int tl = w * 2 + tt;
        const float* q = qs + tl * 64;
        float sc[4];
#pragma unroll
        for (int k = 0; k < 4; k++) {
            const float* er = encp + (lane + k * 32) * 65;
            float acc = 0.f;
#pragma unroll 16
            for (int u = 0; u < 64; u++) acc += q[u] * er[u];
            sc[k] = acc;
        }
        float m = fmaxf(fmaxf(sc[0], sc[1]), fmaxf(sc[2], sc[3]));
#pragma unroll
        for (int st = 16; st; st >>= 1)
            m = fmaxf(m, __shfl_xor_sync(0xffffffffu, m, st));
        float sum = 0.f;
#pragma unroll
        for (int k = 0; k < 4; k++) { sc[k] = __expf(sc[k] - m); sum += sc[k]; }
#pragma unroll
        for (int st = 16; st; st >>= 1)
            sum += __shfl_xor_sync(0xffffffffu, sum, st);
        float inv = 1.f / sum;
#pragma unroll
        for (int k = 0; k < 4; k++) att[tl * 128 + lane + k * 32] = sc[k] * inv;
    }
    __syncwarp();
#pragma unroll 1
    for (int tt = 0; tt < 2; tt++) {
        int tl = w * 2 + tt;
        size_t row = (size_t)b * TT + tc * 16 + tl;
        const float* at = att + tl * 128;
#pragma unroll 1
        for (int h = 0; h < 2; h++) {
            int u = lane + h * 32;
            float acc = 0.f;
#pragma unroll 16
            for (int s = 0; s < 128; s++) acc += at[s] * encp[s * 65 + u];
            g_Ah[row * 128 + UNITS + u] = __float2half(acc);
            g_Ah[row * 128 + u] = __float2half(g_hs[row * UNITS + u]);
        }
    }
}

// ---------------- streaming fp16 GEMM: A resident, B double-buffered ------
// each CTA: one 128-row block x TPC col tiles. exp(logit+bd) -> g_eh fp16,
// per-(coltile, wc) row partials -> g_partial (no atomics).
__device__ __forceinline__ void loadB(uint32_t dst, const __half* gB, int tid) {
#pragma unroll
    for (int it = 0; it < 8; it++) {
        int idx = tid + it * 256;
        int r = idx >> 4, cqb = (idx & 15) * 16;
        cp16(dst + r * (PADK * 2) + cqb, (const char*)gB + (size_t)r * 256 + cqb);
    }
}

__global__ __launch_bounds__(256, 2) void k_mma(const float* __restrict__ bd) {
    extern __shared__ __half hsm[];
    uint32_t sb = smem_u32(hsm);
    int tid = threadIdx.x;
    int rowBase = blockIdx.y * BM;
    int ct0 = blockIdx.x * TPC;

    // group 0: A tile + B tile 0
    {
        const __half* gA = g_Ah + (size_t)rowBase * 128;
#pragma unroll
        for (int it = 0; it < 8; it++) {
            int idx = tid + it * 256;
            int r = idx >> 4, cqb = (idx & 15) * 16;
            cp16(sb + r * (PADK * 2) + cqb,
                 (const char*)gA + (size_t)r * 256 + cqb);
        }
        loadB(sb + AS_BYTES, g_Wh + (size_t)ct0 * BN * 128, tid);
        CP_COMMIT();
    }

    int lane = tid & 31, w = tid >> 5;
    int wr = w >> 2, wc = w & 3;
    int g = lane >> 2, t = lane & 3;
    int mq = lane >> 3, rq = lane & 7;

    uint32_t aAddr[4];
#pragma unroll
    for (int i = 0; i < 4; i++)
        aAddr[i] = sb + (((wr * 64 + i * 16 + (mq & 1) * 8 + rq) * PADK) +
                         (mq >> 1) * 8) * 2;
    uint32_t bRel0 = (((wc * 32 + (mq >> 1) * 8 + rq) * PADK) + (mq & 1) * 8) * 2;
    uint32_t bRel1 = bRel0 + 16 * PADK * 2;

#pragma unroll 1
    for (int tt = 0; tt < TPC; tt++) {
        if (tt + 1 < TPC) {
            loadB(sb + AS_BYTES + ((tt + 1) & 1) * BS_BYTES,
                  g_Wh + (size_t)(ct0 + tt + 1) * BN * 128, tid);
            CP_COMMIT();
            CP_WAIT1();
        } else {
            CP_WAIT0();
        }
        __syncthreads();

        uint32_t bBase = sb + AS_BYTES + (tt & 1) * BS_BYTES;
        float c[4][4][4];
#pragma unroll
        for (int i = 0; i < 4; i++)
#pragma unroll
            for (int j = 0; j < 4; j++)
#pragma unroll
                for (int k = 0; k < 4; k++) c[i][j][k] = 0.f;

#pragma unroll
        for (int k0 = 0; k0 < 8; k0++) {
            uint32_t a[4][4], bb[8];
#pragma unroll
            for (int i = 0; i < 4; i++) ldm_x4(a[i], aAddr[i] + k0 * 32);
            ldm_x4(bb, bBase + bRel0 + k0 * 32);
            ldm_x4(bb + 4, bBase + bRel1 + k0 * 32);
#pragma unroll
            for (int i = 0; i < 4; i++)
#pragma unroll
                for (int j = 0; j < 4; j++) mma_f16(c[i][j], a[i], bb + j * 2);
        }
        __syncthreads();   // all warps done reading this B buffer

        // epilogue (no barriers): exp, store fp16, per-quad partials
        int colBase = (ct0 + tt) * BN;
        float rs[4][2];
#pragma unroll
        for (int i = 0; i < 4; i++) { rs[i][0] = 0.f; rs[i][1] = 0.f; }
#pragma unroll
        for (int i = 0; i < 4; i++) {
            int row0 = rowBase + wr * 64 + i * 16 + g;
#pragma unroll
            for (int j = 0; j < 4; j++) {
                int cl = wc * 32 + j * 8 + 2 * t;
                float2 bdv = __ldg((const float2*)(bd + colBase + cl));
                float e00 = __expf(c[i][j][0] + bdv.x);
                float e01 = __expf(c[i][j][1] + bdv.y);
                float e10 = __expf(c[i][j][2] + bdv.x);
                float e11 = __expf(c[i][j][3] + bdv.y);
                rs[i][0] += e00 + e01;
                rs[i][1] += e10 + e11;
                *(__half2*)&g_eh[(size_t)row0 * VOCAB + colBase + cl] =
                    __floats2half2_rn(e00, e01);
                *(__half2*)&g_eh[(size_t)(row0 + 8) * VOCAB + colBase + cl] =
                    __floats2half2_rn(e10, e11);
            }
        }
        float* gp = g_partial + ((size_t)(ct0 + tt) * 4 + wc) * NROWS + rowBase;
#pragma unroll
        for (int i = 0; i < 4; i++) {
#pragma unroll
            for (int h = 0; h < 2; h++) {
                rs[i][h] += __shfl_xor_sync(0xffffffffu, rs[i][h], 1);
                rs[i][h] += __shfl_xor_sync(0xffffffffu, rs[i][h], 2);
            }
            if (t == 0) {
                gp[wr * 64 + i * 16 + g] = rs[i][0];
                gp[wr * 64 + i * 16 + g + 8] = rs[i][1];
            }
        }
    }
}

// ---------------- reduce partials -> 1/rowsum ----------------
__global__ __launch_bounds__(256) void k_rowsum() {
    int row = blockIdx.x * 256 + threadIdx.x;
    float s = 0.f;
    for (int j = 0; j < NT * 4; j++) s += g_partial[(size_t)j * NROWS + row];
    g_inv[row] = 1.f / s;
}

// ---------------- normalize: out = fp16(exp) * inv[row], streaming ----------
__global__ __launch_bounds__(256) void k_norm(float* __restrict__ out) {
    size_t i8 = (size_t)blockIdx.x * 256 + threadIdx.x;
    int row = (int)(i8 / (VOCAB / 8));
    float inv = g_inv[row];
    const uint4 v = *(const uint4*)(g_eh + i8 * 8);
    const __half2* h = (const __half2*)&v;
    float4 o0, o1;
    float2 f;
    f = __half22float2(h[0]); o0.x = f.x * inv; o0.y = f.y * inv;
    f = __half22float2(h[1]); o0.z = f.x * inv; o0.w = f.y * inv;
    f = __half22float2(h[2]); o1.x = f.x * inv; o1.y = f.y * inv;
    f = __half22float2(h[3]); o1.z = f.x * inv; o1.w = f.y * inv;
    float4* op = (float4*)(out + i8 * 8);
    op[0] = o0;
    op[1] = o1;
}

// ---------------- launch ----------------
extern "C" void kernel_launch(void* const* d_in, const int* in_sizes, int n_in,
                              void* d_out, int out_size) {
    const float* enc = (const float*)d_in[0];
    const int*   dec = (const int*)d_in[1];
    const float* h0  = (const float*)d_in[2];
    const float* c0  = (const float*)d_in[3];
    const float* emb = (const float*)d_in[4];
    const float* Wx  = (const float*)d_in[5];
    const float* Wh  = (const float*)d_in[6];
    const float* bv  = (const float*)d_in[7];
    const float* Wd  = (const float*)d_in[8];
    const float* bd  = (const float*)d_in[9];
    float* out = (float*)d_out;

    cudaFuncSetAttribute(k_mma, cudaFuncAttributeMaxDynamicSharedMemorySize,
                         SMEM_MMA);

    k_cvtWd<<<dim3(VOCAB / 32, 4), 256>>>(Wd);
    k_xz<<<256, 256>>>(dec, emb, Wx, bv);
    k_lstm<<<NB, 256>>>(h0, c0, Wh, out + (size_t)NROWS * VOCAB);
    k_attn<<<dim3(TT / 16, NB), 256>>>(enc, h0);
    k_mma<<<dim3(NCT, NROWS / BM), 256, SMEM_MMA>>>(bd);
    k_rowsum<<<NROWS / 256, 256>>>();
    k_norm<<<(NROWS * (VOCAB / 8)) / 256, 256>>>(out);
}

// round 17
// speedup vs baseline: 1.0750x; 1.0750x over previous
#include <cuda_runtime.h>
#include <cuda_fp16.h>
#include <cstdint>

#define NROWS 4096      // B*T
#define VOCAB 32000
#define UNITS 64
#define GATES 256
#define EMBED 512
#define TT 128
#define NB 32

#define BM 128
#define BN 128
#define NT (VOCAB / BN)          // 250 col tiles
#define PADK 136

#define AS_H (BM * PADK)
#define BS_H (BN * PADK)
#define SMEM_MMA (AS_H * 2 + BS_H * 2 + 256 * 4 + 16)

// ---------------- device scratch ----------------
__device__ __align__(256) float g_xz[NROWS * GATES];
__device__ __align__(256) float g_hs[NROWS * UNITS];
__device__ __align__(256) __half g_Ah[NROWS * 128];            // feat fp16
__device__ __align__(256) __half g_Wh[(size_t)VOCAB * 128];    // Wd^T fp16
__device__ __align__(256) __half g_eh[(size_t)NROWS * VOCAB];  // exp fp16
__device__ __align__(256) float g_partial[(size_t)NT * NROWS];
__device__ __align__(256) float g_inv[NROWS];

__device__ __forceinline__ void mma_f16(float* c, const uint32_t* a,
                                        const uint32_t* b) {
    asm volatile(
        "mma.sync.aligned.m16n8k16.row.col.f32.f16.f16.f32 "
        "{%0,%1,%2,%3}, {%4,%5,%6,%7}, {%8,%9}, {%0,%1,%2,%3};"
        : "+f"(c[0]), "+f"(c[1]), "+f"(c[2]), "+f"(c[3])
        : "r"(a[0]), "r"(a[1]), "r"(a[2]), "r"(a[3]), "r"(b[0]), "r"(b[1]));
}
__device__ __forceinline__ void ldm_x4(uint32_t* r, uint32_t addr) {
    asm volatile("ldmatrix.sync.aligned.m8n8.x4.shared.b16 {%0,%1,%2,%3}, [%4];"
                 : "=r"(r[0]), "=r"(r[1]), "=r"(r[2]), "=r"(r[3]) : "r"(addr));
}
__device__ __forceinline__ uint32_t smem_u32(const void* p) {
    uint32_t a;
    asm("{ .reg .u64 t; cvta.to.shared.u64 t, %1; cvt.u32.u64 %0, t; }"
        : "=r"(a) : "l"(p));
    return a;
}
__device__ __forceinline__ void cp16(uint32_t dst, const void* src) {
    asm volatile("cp.async.ca.shared.global [%0], [%1], 16;"
                 :: "r"(dst), "l"(src) : "memory");
}
#define CP_COMMIT() asm volatile("cp.async.commit_group;" ::: "memory")
#define CP_WAIT0()  asm volatile("cp.async.wait_group 0;" ::: "memory")

// ---------------- kernel: Wd [128][32000] f32 -> g_Wh [32000][128] fp16 ----
__global__ __launch_bounds__(256) void k_cvtWd(const float* __restrict__ Wd) {
    __shared__ float sm[32][33];
    int tx = threadIdx.x & 31, ty = threadIdx.x >> 5;
    int v0 = blockIdx.x * 32, k0 = blockIdx.y * 32;
#pragma unroll
    for (int i = 0; i < 4; i++) {
        int k = ty + i * 8;
        sm[k][tx] = Wd[(size_t)(k0 + k) * VOCAB + v0 + tx];
    }
    __syncthreads();
#pragma unroll
    for (int i = 0; i < 4; i++) {
        int vl = ty + i * 8;
        g_Wh[(size_t)(v0 + vl) * 128 + k0 + tx] = __float2half(sm[tx][vl]);
    }
}

// ---------------- kernel A: xz = emb[dec] @ Wx + b ----------------
__global__ __launch_bounds__(256) void k_xz(const int* __restrict__ dec,
                                            const float* __restrict__ emb,
                                            const float* __restrict__ Wx,
                                            const float* __restrict__ bvec) {
    __shared__ float xs[16 * EMBED];
    __shared__ int tok[16];
    int tid = threadIdx.x;
    int rowBase = blockIdx.x * 16;
    if (tid < 16) tok[tid] = dec[rowBase + tid];
    __syncthreads();
    for (int i = tid; i < 16 * (EMBED / 4); i += 256) {
        int r = i >> 7, q = i & 127;
        ((float4*)xs)[r * (EMBED / 4) + q] =
            ((const float4*)(emb + (size_t)tok[r] * EMBED))[q];
    }
    __syncthreads();
    int g = tid;
    float bb = bvec[g];
    float acc[16];
#pragma unroll
    for (int r = 0; r < 16; r++) acc[r] = bb;
#pragma unroll 4
    for (int e = 0; e < EMBED; e++) {
        float w = Wx[e * GATES + g];
#pragma unroll
        for (int r = 0; r < 16; r++) acc[r] += xs[r * EMBED + e] * w;
    }
#pragma unroll
    for (int r = 0; r < 16; r++) g_xz[(size_t)(rowBase + r) * GATES + g] = acc[r];
}

// ---------------- kernel B: sequential LSTM ----------------
__global__ __launch_bounds__(256) void k_lstm(const float* __restrict__ h0,
                                              const float* __restrict__ c0,
                                              const float* __restrict__ Wh,
                                              float* __restrict__ tail) {
    int b = blockIdx.x;
    int g = threadIdx.x;
    float wh[UNITS];
#pragma unroll
    for (int u = 0; u < UNITS; u++) wh[u] = Wh[u * GATES + g];
    __shared__ __align__(16) float sh_h[UNITS];
    __shared__ float sh_z[GATES];
    float c = 0.f;
    if (g < UNITS) {
        sh_h[g] = h0[b * UNITS + g];
        c = c0[b * UNITS + g];
    }
    __syncthreads();
    for (int t = 0; t < TT; t++) {
        float z = g_xz[((size_t)b * TT + t) * GATES + g];
#pragma unroll
        for (int u4 = 0; u4 < UNITS / 4; u4++) {
            float4 h4 = ((const float4*)sh_h)[u4];
            z += h4.x * wh[u4 * 4] + h4.y * wh[u4 * 4 + 1] +
                 h4.z * wh[u4 * 4 + 2] + h4.w * wh[u4 * 4 + 3];
        }
        sh_z[g] = z;
        __syncthreads();
        if (g < UNITS) {
            float ig = 1.f / (1.f + expf(-sh_z[g]));
            float fg = 1.f / (1.f + expf(-sh_z[UNITS + g]));
            float gg = tanhf(sh_z[2 * UNITS + g]);
            float og = 1.f / (1.f + expf(-sh_z[3 * UNITS + g]));
            c = fg * c + ig * gg;
            float h = og * tanhf(c);
            sh_h[g] = h;
            g_hs[((size_t)b * TT + t) * UNITS + g] = h;
        }
        __syncthreads();
    }
    if (g < UNITS) {
        tail[b * UNITS + g] = sh_h[g];
        tail[NB * UNITS + b * UNITS + g] = c;
    }
}

// ---------------- kernel C: attention (per-b 16-t chunks) -> fp16 feat ----
__global__ __launch_bounds__(256) void k_attn(const float* __restrict__ enc,
                                              const float* __restrict__ h0) {
    __shared__ float encp[TT * 65];
    __shared__ float qs[16 * 64];
    __shared__ float att[16 * 128];
    int tid = threadIdx.x;
    int b = blockIdx.y, tc = blockIdx.x;
    const float* eb = enc + (size_t)b * TT * UNITS;
    for (int i = tid; i < TT * UNITS; i += 256) {
        int s = i >> 6, u = i & 63;
        encp[s * 65 + u] = eb[i];
    }
    for (int i = tid; i < 16 * 64; i += 256) {
        int tl = i >> 6, u = i & 63;
        int t = tc * 16 + tl;
        qs[i] = (t == 0) ? h0[b * 64 + u]
                         : g_hs[((size_t)b * TT + t - 1) * 64 + u];
    }
    __syncthreads();
    int w = tid >> 5, lane = tid & 31;
#pragma unroll 1
    for (int tt = 0; tt < 2; tt++) {
        int tl = w * 2 + tt;
        const float* q = qs + tl * 64;
        float sc[4];
#pragma unroll
        for (int k = 0; k < 4; k++) {
            const float* er = encp + (lane + k * 32) * 65;
            float acc = 0.f;
#pragma unroll 16
            for (int u = 0; u < 64; u++) acc += q[u] * er[u];
            sc[k] = acc;
        }
        float m = fmaxf(fmaxf(sc[0], sc[1]), fmaxf(sc[2], sc[3]));
#pragma unroll
        for (int st = 16; st; st >>= 1)
            m = fmaxf(m, __shfl_xor_sync(0xffffffffu, m, st));
        float sum = 0.f;
#pragma unroll
        for (int k = 0; k < 4; k++) { sc[k] = __expf(sc[k] - m); sum += sc[k]; }
#pragma unroll
        for (int st = 16; st; st >>= 1)
            sum += __shfl_xor_sync(0xffffffffu, sum, st);
        float inv = 1.f / sum;
#pragma unroll
        for (int k = 0; k < 4; k++) att[tl * 128 + lane + k * 32] = sc[k] * inv;
    }
    __syncwarp();
#pragma unroll 1
    for (int tt = 0; tt < 2; tt++) {
        int tl = w * 2 + tt;
        size_t row = (size_t)b * TT + tc * 16 + tl;
        const float* at = att + tl * 128;
#pragma unroll 1
        for (int h = 0; h < 2; h++) {
            int u = lane + h * 32;
            float acc = 0.f;
#pragma unroll 16
            for (int s = 0; s < 128; s++) acc += at[s] * encp[s * 65 + u];
            g_Ah[row * 128 + UNITS + u] = __float2half(acc);
            g_Ah[row * 128 + u] = __float2half(g_hs[row * UNITS + u]);
        }
    }
}

// ---------------- fp16 m16n8k16 GEMM, single pass, staged stores ----------
__global__ __launch_bounds__(256, 2) void k_mma(const float* __restrict__ bd) {
    extern __shared__ __half hsm[];
    float* srow = (float*)(hsm + AS_H + BS_H);
    float* sbd = srow + 128;
    uint32_t sb = smem_u32(hsm);

    int tid = threadIdx.x;
    int colBase = blockIdx.x * BN;
    int rowBase = blockIdx.y * BM;

    {
        const __half* gA = g_Ah + (size_t)rowBase * 128;
        const __half* gB = g_Wh + (size_t)colBase * 128;
#pragma unroll
        for (int it = 0; it < 8; it++) {
            int idx = tid + it * 256;
            int r = idx >> 4, cqb = (idx & 15) * 16;
            cp16(sb + r * (PADK * 2) + cqb, (const char*)gA + (size_t)r * 256 + cqb);
        }
#pragma unroll
        for (int it = 0; it < 8; it++) {
            int idx = tid + it * 256;
            int r = idx >> 4, cqb = (idx & 15) * 16;
            cp16(sb + AS_H * 2 + r * (PADK * 2) + cqb,
                 (const char*)gB + (size_t)r * 256 + cqb);
        }
        CP_COMMIT();
    }
    if (tid < 128) {
        sbd[tid] = bd[colBase + tid];
        srow[tid] = 0.f;
    }
    CP_WAIT0();
    __syncthreads();

    int lane = tid & 31, w = tid >> 5;
    int wr = w >> 2, wc = w & 3;
    int g = lane >> 2, t = lane & 3;
    int mq = lane >> 3, rq = lane & 7;

    uint32_t aAddr[4];
#pragma unroll
    for (int i = 0; i < 4; i++)
        aAddr[i] = sb + (((wr * 64 + i * 16 + (mq & 1) * 8 + rq) * PADK) +
                         (mq >> 1) * 8) * 2;
    uint32_t bAddr0 = sb + AS_H * 2 +
                      (((wc * 32 + (mq >> 1) * 8 + rq) * PADK) + (mq & 1) * 8) * 2;
    uint32_t bAddr1 = bAddr0 + 16 * PADK * 2;

    float c[4][4][4];
#pragma unroll
    for (int i = 0; i < 4; i++)
#pragma unroll
        for (int j = 0; j < 4; j++)
#pragma unroll
            for (int k = 0; k < 4; k++) c[i][j][k] = 0.f;

#pragma unroll
    for (int k0 = 0; k0 < 8; k0++) {
        uint32_t a[4][4], bb[8];
#pragma unroll
        for (int i = 0; i < 4; i++) ldm_x4(a[i], aAddr[i] + k0 * 32);
        ldm_x4(bb, bAddr0 + k0 * 32);
        ldm_x4(bb + 4, bAddr1 + k0 * 32);
#pragma unroll
        for (int i = 0; i < 4; i++)
#pragma unroll
            for (int j = 0; j < 4; j++) mma_f16(c[i][j], a[i], bb + j * 2);
    }
    __syncthreads();   // A/B smem dead from here — reuse A region as staging

    __half* stage = hsm;   // [128][PADK] halves
    float rs[4][2];
#pragma unroll
    for (int i = 0; i < 4; i++) { rs[i][0] = 0.f; rs[i][1] = 0.f; }
#pragma unroll
    for (int i = 0; i < 4; i++) {
        int rl0 = wr * 64 + i * 16 + g;
#pragma unroll
        for (int j = 0; j < 4; j++) {
            int cl = wc * 32 + j * 8 + 2 * t;
            float b0 = sbd[cl], b1 = sbd[cl + 1];
            float e00 = __expf(c[i][j][0] + b0);
            float e01 = __expf(c[i][j][1] + b1);
            float e10 = __expf(c[i][j][2] + b0);
            float e11 = __expf(c[i][j][3] + b1);
            rs[i][0] += e00 + e01;
            rs[i][1] += e10 + e11;
            *(__half2*)&stage[rl0 * PADK + cl] = __floats2half2_rn(e00, e01);
            *(__half2*)&stage[(rl0 + 8) * PADK + cl] = __floats2half2_rn(e10, e11);
        }
    }
#pragma unroll
    for (int i = 0; i < 4; i++) {
#pragma unroll
        for (int h = 0; h < 2; h++) {
            rs[i][h] += __shfl_xor_sync(0xffffffffu, rs[i][h], 1);
            rs[i][h] += __shfl_xor_sync(0xffffffffu, rs[i][h], 2);
        }
        if (t == 0) {
            atomicAdd(&srow[wr * 64 + i * 16 + g], rs[i][0]);
            atomicAdd(&srow[wr * 64 + i * 16 + g + 8], rs[i][1]);
        }
    }
    __syncthreads();
    // coalesced store: 128 rows x 16 chunks of 16B (256B contiguous per row)
#pragma unroll
    for (int it = 0; it < 8; it++) {
        int idx = tid + it * 256;
        int r = idx >> 4, q = idx & 15;
        uint4 v = *(const uint4*)(stage + r * PADK + q * 8);
        *(uint4*)&g_eh[(size_t)(rowBase + r) * VOCAB + colBase + q * 8] = v;
    }
    if (tid < 128)
        g_partial[(size_t)blockIdx.x * NROWS + rowBase + tid] = srow[tid];
}

// ---------------- reduce partials -> 1/rowsum ----------------
__global__ __launch_bounds__(256) void k_rowsum() {
    int row = blockIdx.x * 256 + threadIdx.x;
    float s = 0.f;
    for (int j = 0; j < NT; j++) s += g_partial[(size_t)j * NROWS + row];
    g_inv[row] = 1.f / s;
}

// ---------------- normalize: out = fp16(exp) * inv[row], streaming ----------
__global__ __launch_bounds__(256) void k_norm(float* __restrict__ out) {
    size_t i8 = (size_t)blockIdx.x * 256 + threadIdx.x;
    int row = (int)(i8 / (VOCAB / 8));
    float inv = g_inv[row];
    const uint4 v = *(const uint4*)(g_eh + i8 * 8);
    const __half2* h = (const __half2*)&v;
    float4 o0, o1;
    float2 f;
    f = __half22float2(h[0]); o0.x = f.x * inv; o0.y = f.y * inv;
    f = __half22float2(h[1]); o0.z = f.x * inv; o0.w = f.y * inv;
    f = __half22float2(h[2]); o1.x = f.x * inv; o1.y = f.y * inv;
    f = __half22float2(h[3]); o1.z = f.x * inv; o1.w = f.y * inv;
    float4* op = (float4*)(out + i8 * 8);
    op[0] = o0;
    op[1] = o1;
}

// ---------------- launch ----------------
extern "C" void kernel_launch(void* const* d_in, const int* in_sizes, int n_in,
                              void* d_out, int out_size) {
    const float* enc = (const float*)d_in[0];
    const int*   dec = (const int*)d_in[1];
    const float* h0  = (const float*)d_in[2];
    const float* c0  = (const float*)d_in[3];
    const float* emb = (const float*)d_in[4];
    const float* Wx  = (const float*)d_in[5];
    const float* Wh  = (const float*)d_in[6];
    const float* bv  = (const float*)d_in[7];
    const float* Wd  = (const float*)d_in[8];
    const float* bd  = (const float*)d_in[9];
    float* out = (float*)d_out;

    cudaFuncSetAttribute(k_mma, cudaFuncAttributeMaxDynamicSharedMemorySize,
                         SMEM_MMA);

    k_cvtWd<<<dim3(VOCAB / 32, 4), 256>>>(Wd);
    k_xz<<<256, 256>>>(dec, emb, Wx, bv);
    k_lstm<<<NB, 256>>>(h0, c0, Wh, out + (size_t)NROWS * VOCAB);
    k_attn<<<dim3(TT / 16, NB), 256>>>(enc, h0);
    k_mma<<<dim3(NT, NROWS / BM), 256, SMEM_MMA>>>(bd);
    k_rowsum<<<NROWS / 256, 256>>>();
    k_norm<<<(NROWS * (VOCAB / 8)) / 256, 256>>>(out);
}